// round 3
// baseline (speedup 1.0000x reference)
#include <cuda_runtime.h>

#define S_  2048
#define D_  64
#define W_  64
#define NW_ (S_ - W_)   // 1984 windows
#define NT_ 256

// Level offsets for the associative-scan pyramid (sizes 2048,1024,...,1 => 4095 floats)
__device__ __constant__ int OFF_[12] = {0,2048,3072,3584,3840,3968,4032,4064,4080,4088,4092,4094};

__global__ __launch_bounds__(NT_) void swl2_pool_kernel(
    const float* __restrict__ x, float* __restrict__ out)
{
    __shared__ float scan[4096];   // level-0 (sq) at [0,2048), pyramid above
    __shared__ float wv[8];
    __shared__ int   wi[8];
    __shared__ int   s_idx;

    const int b    = blockIdx.x;
    const int tid  = threadIdx.x;
    const int lane = tid & 31;
    const int warp = tid >> 5;

    const float* xrow = x + (size_t)b * S_ * D_;

    // ---- Phase A: sq[r] = sum(x[r]^2) with XLA-GPU row-reduction bracketing ----
    // t_l = x2[l] + x2[l+32]; then shuffle tree offsets 16,8,4,2,1 (lane 0's bracketing).
    // __fmul_rn/__fadd_rn forbid FMA contraction (rounding must match x*x then add).
    #pragma unroll 1
    for (int it = 0; it < S_ / 32; ++it) {           // 64 iterations, 4 rows/warp/iter
        const int r = it * 32 + warp * 4;
        const float* p = xrow + (size_t)r * D_;
        float a0 = p[      lane], b0 = p[      lane + 32];
        float a1 = p[ 64 + lane], b1 = p[ 64 + lane + 32];
        float a2 = p[128 + lane], b2 = p[128 + lane + 32];
        float a3 = p[192 + lane], b3 = p[192 + lane + 32];
        float t0 = __fadd_rn(__fmul_rn(a0, a0), __fmul_rn(b0, b0));
        float t1 = __fadd_rn(__fmul_rn(a1, a1), __fmul_rn(b1, b1));
        float t2 = __fadd_rn(__fmul_rn(a2, a2), __fmul_rn(b2, b2));
        float t3 = __fadd_rn(__fmul_rn(a3, a3), __fmul_rn(b3, b3));
        #pragma unroll
        for (int off = 16; off; off >>= 1) {
            t0 = __fadd_rn(t0, __shfl_xor_sync(0xffffffffu, t0, off));
            t1 = __fadd_rn(t1, __shfl_xor_sync(0xffffffffu, t1, off));
            t2 = __fadd_rn(t2, __shfl_xor_sync(0xffffffffu, t2, off));
            t3 = __fadd_rn(t3, __shfl_xor_sync(0xffffffffu, t3, off));
        }
        if (lane == 0) {
            scan[r + 0] = t0; scan[r + 1] = t1;
            scan[r + 2] = t2; scan[r + 3] = t3;
        }
    }
    __syncthreads();

    // ---- Phase B: JAX associative_scan cumsum, bit-exact bracketing ----
    // Down-sweep: R_{k+1}[i] = R_k[2i] + R_k[2i+1]
    #pragma unroll
    for (int k = 0; k < 11; ++k) {
        const int src = OFF_[k], dst = OFF_[k + 1];
        const int m = 2048 >> (k + 1);
        for (int i = tid; i < m; i += NT_)
            scan[dst + i] = __fadd_rn(scan[src + 2*i], scan[src + 2*i + 1]);
        __syncthreads();
    }
    // Up-sweep: S_k[2i+1] = S_{k+1}[i]; S_k[2i] = S_{k+1}[i-1] + R_k[2i] (i>0)
    #pragma unroll
    for (int k = 10; k >= 0; --k) {
        const int ok = OFF_[k], ok1 = OFF_[k + 1];
        const int m = 2048 >> (k + 1);
        for (int i = tid; i < m; i += NT_) {
            const float so = scan[ok1 + i];
            if (i > 0)
                scan[ok + 2*i] = __fadd_rn(scan[ok1 + i - 1], scan[ok + 2*i]);
            scan[ok + 2*i + 1] = so;
        }
        __syncthreads();
    }
    // Now scan[0..2047] = cumsum(sq) with JAX's exact fp32 rounding.

    // ---- Phase C: win[j] = c[j+64] - c[j]; local argmax over 8 windows/thread ----
    float best = -3.402823466e+38f;
    int   bidx = 0x7fffffff;
    const int j0 = tid * 8;
    if (j0 < NW_) {                                  // threads 0..247 active
        #pragma unroll
        for (int j = j0; j < j0 + 8; ++j) {
            const float cl = (j == 0) ? 0.0f : scan[j - 1];
            const float w  = __fadd_rn(scan[j + W_ - 1], -cl);
            if (w > best) { best = w; bidx = j; }    // strict > => first occurrence
        }
    }

    // ---- Phase D: block argmax (max value, min index on exact ties) ----
    #pragma unroll
    for (int off = 16; off; off >>= 1) {
        float ov = __shfl_xor_sync(0xffffffffu, best, off);
        int   oi = __shfl_xor_sync(0xffffffffu, bidx, off);
        if (ov > best || (ov == best && oi < bidx)) { best = ov; bidx = oi; }
    }
    if (lane == 0) { wv[warp] = best; wi[warp] = bidx; }
    __syncthreads();
    if (tid == 0) {
        float bv = wv[0]; int bi = wi[0];
        #pragma unroll
        for (int i = 1; i < 8; ++i)
            if (wv[i] > bv || (wv[i] == bv && wi[i] < bi)) { bv = wv[i]; bi = wi[i]; }
        s_idx = bi;
    }
    __syncthreads();

    // ---- Phase E: gather 64 rows (16 KB) to output, coalesced float4 ----
    const int idx = s_idx;
    const float4* src = (const float4*)(xrow + (size_t)idx * D_);
    float4* dst = (float4*)(out + (size_t)b * W_ * D_);
    #pragma unroll
    for (int i = 0; i < (W_ * 16) / NT_; ++i)        // 4 float4 per thread
        dst[i * NT_ + tid] = src[i * NT_ + tid];
}

extern "C" void kernel_launch(void* const* d_in, const int* in_sizes, int n_in,
                              void* d_out, int out_size)
{
    const float* x = (const float*)d_in[0];
    float* out = (float*)d_out;
    const int B = in_sizes[0] / (S_ * D_);   // 1024 for this problem
    swl2_pool_kernel<<<B, NT_>>>(x, out);
}